// round 3
// baseline (speedup 1.0000x reference)
#include <cuda_runtime.h>
#include <cstdint>

#define N_NODES    100000
#define EMB_DIM    128
#define BATCH      16384
#define NUM_SAMPLE 25

// EMB_DIM/4 float4s per row = 32 -> one lane per float4.
#define VEC_PER_ROW (EMB_DIM / 4)   // 32

__global__ __launch_bounds__(256) void mean_agg_kernel(
    const float4* __restrict__ emb,      // [N_NODES, 32] as float4
    const int* __restrict__ neigh,       // [BATCH, NUM_SAMPLE], int32
    float4* __restrict__ out)            // [BATCH, 32] as float4
{
    const int warp_id = (blockIdx.x * blockDim.x + threadIdx.x) >> 5;
    const int lane    = threadIdx.x & 31;
    if (warp_id >= BATCH) return;

    // Each lane < NUM_SAMPLE holds one neighbor index for this row.
    const int* nb = neigh + warp_id * NUM_SAMPLE;
    int my_idx = (lane < NUM_SAMPLE) ? nb[lane] : 0;

    float4 acc = make_float4(0.f, 0.f, 0.f, 0.f);

    #pragma unroll
    for (int s = 0; s < NUM_SAMPLE; ++s) {
        int id = __shfl_sync(0xffffffffu, my_idx, s);
        float4 v = __ldg(&emb[(unsigned)id * VEC_PER_ROW + lane]);
        acc.x += v.x;
        acc.y += v.y;
        acc.z += v.z;
        acc.w += v.w;
    }

    const float inv = 1.0f / (float)NUM_SAMPLE;   // 0.04
    acc.x *= inv; acc.y *= inv; acc.z *= inv; acc.w *= inv;

    out[(unsigned)warp_id * VEC_PER_ROW + lane] = acc;
}

extern "C" void kernel_launch(void* const* d_in, const int* in_sizes, int n_in,
                              void* d_out, int out_size)
{
    const float4* emb   = (const float4*)d_in[0];
    const int*    neigh = (const int*)d_in[1];
    float4*       out   = (float4*)d_out;

    // One warp per row, 8 warps (256 threads) per block.
    const int threads = 256;
    const int warps_per_block = threads / 32;
    const int blocks = (BATCH + warps_per_block - 1) / warps_per_block;

    mean_agg_kernel<<<blocks, threads>>>(emb, neigh, out);
}